// round 4
// baseline (speedup 1.0000x reference)
#include <cuda_runtime.h>

// LaneAttention fused, fp32 + packed f32x2 FMA, sm_103a. 2 CTAs/SM.
// One block per (b,v). 512 threads. t processed in halves of 16.

#define TT   30
#define FF   128
#define LL   64
#define LFN  64
#define NH   4
#define HD   32
#define THN  20
#define NBLK 2048
#define NTHR 512

typedef unsigned long long u64;

// SMEM regions (float offsets)
#define KT_OFF 0          // Kt[128 g][65]  (g-major, stride 65)
#define W_OFF  8320       // weight tile: Wt[f][130] (K/V) or W[g][66] (Q/Y); P overlays
#define P_OFF  8320       // sP[16][256]
#define V_OFF  16768      // sV[64 l][128 g]
#define X_OFF  24960      // sX[16][128]; sO overlays; LN[64][64] overlays X+Q
#define O_OFF  24960
#define LN_OFF 24960
#define Q_OFF  27008      // sQ[16][128]
#define SMEM_FLOATS 29056 // 116224 bytes -> 2 CTAs/SM (232448 <= 233472)

__device__ __forceinline__ u64 ffma2(u64 a, u64 b, u64 c) {
    u64 d;
    asm("fma.rn.f32x2 %0, %1, %2, %3;" : "=l"(d) : "l"(a), "l"(b), "l"(c));
    return d;
}
__device__ __forceinline__ u64 dup2(float x) {
    u64 d; asm("mov.b64 %0, {%1, %1};" : "=l"(d) : "f"(x)); return d;
}
__device__ __forceinline__ u64 pack2(float lo, float hi) {
    u64 d; asm("mov.b64 %0, {%1, %2};" : "=l"(d) : "f"(lo), "f"(hi)); return d;
}
__device__ __forceinline__ float2 unpack2(u64 a) {
    float2 r; asm("mov.b64 {%0, %1}, %2;" : "=f"(r.x), "=f"(r.y) : "l"(a)); return r;
}

// Wk/Wv: transposed tile Wt[f][g], stride 130 (even offsets for per-lane LDS.64 pairs)
__device__ __forceinline__ void load_wt(float* sm, const float* Wsrc, int tid) {
    for (int idx = tid; idx < 128 * 64; idx += NTHR) {
        int g = idx >> 6, f = idx & 63;
        sm[W_OFF + f * 130 + g] = Wsrc[g * 64 + f];
    }
}
// Wq/Wc halves: g-major tile W[g][f], stride 66 (even -> aligned f-pair LDS.64)
__device__ __forceinline__ void load_w66(float* sm, const float* Wsrc,
                                         int foff, int tid) {
    for (int idx = tid; idx < 128 * 64; idx += NTHR) {
        int g = idx >> 6, f = idx & 63;
        sm[W_OFF + g * 66 + f] = Wsrc[g * FF + foff + f];
    }
}

__global__ void __launch_bounds__(NTHR, 2)
lane_attn_kernel(const float* __restrict__ veh,
                 const float* __restrict__ lanes,
                 const int* __restrict__ maskl,
                 const float* __restrict__ Wk, const float* __restrict__ Wv,
                 const float* __restrict__ Wq, const float* __restrict__ Wc,
                 float* __restrict__ out)
{
    extern __shared__ float sm[];
    const int tid  = threadIdx.x;
    const int w    = tid >> 5;
    const int lane = tid & 31;
    const int bid  = blockIdx.x;

    // ---------- mask in registers ----------
    int mi0 = 0, mi1 = 0;
    #pragma unroll
    for (int th = 0; th < THN; th++) {
        const int* mp = maskl + (size_t)(th * NBLK + bid) * LL;
        mi0 |= mp[lane];
        mi1 |= mp[lane + 32];
    }
    const bool km0 = (mi0 != 0), km1 = (mi1 != 0);

    // ---------- load lanes + Wk^T ----------
    {
        const float* lp = lanes + (size_t)bid * (LL * LFN);
        for (int idx = tid; idx < LL * LFN; idx += NTHR) sm[LN_OFF + idx] = lp[idx];
        load_wt(sm, Wk, tid);
    }
    __syncthreads();

    // ---------- K phase: Kt[g][l], output-paired FFMA2 ----------
    // warp w: rows l0 = 4w; lane: g-pairs (2*lane + 64c, +1), c<2
    {
        const int l0 = w * 4;
        u64 acc[4][2];
        #pragma unroll
        for (int r = 0; r < 4; r++) { acc[r][0] = 0; acc[r][1] = 0; }
        #pragma unroll 2
        for (int f = 0; f < LFN; f += 4) {
            float a[4][4];
            #pragma unroll
            for (int r = 0; r < 4; r++) {
                float4 t = *(const float4*)&sm[LN_OFF + (l0 + r) * 64 + f];
                a[r][0] = t.x; a[r][1] = t.y; a[r][2] = t.z; a[r][3] = t.w;
            }
            #pragma unroll
            for (int j = 0; j < 4; j++) {
                u64 w0 = *(const u64*)&sm[W_OFF + (f + j) * 130 + 2 * lane];
                u64 w1 = *(const u64*)&sm[W_OFF + (f + j) * 130 + 2 * lane + 64];
                #pragma unroll
                for (int r = 0; r < 4; r++) {
                    u64 av = dup2(a[r][j]);
                    acc[r][0] = ffma2(av, w0, acc[r][0]);
                    acc[r][1] = ffma2(av, w1, acc[r][1]);
                }
            }
        }
        #pragma unroll
        for (int c = 0; c < 2; c++)
            #pragma unroll
            for (int r = 0; r < 4; r++) {
                float2 v = unpack2(acc[r][c]);
                int g = 2 * lane + 64 * c;
                sm[KT_OFF + g       * 65 + l0 + r] = v.x;
                sm[KT_OFF + (g + 1) * 65 + l0 + r] = v.y;
            }
    }
    __syncthreads();
    load_wt(sm, Wv, tid);
    __syncthreads();

    // ---------- V phase: sV[l][g], paired stores (STS.64) ----------
    {
        const int l0 = w * 4;
        u64 acc[4][2];
        #pragma unroll
        for (int r = 0; r < 4; r++) { acc[r][0] = 0; acc[r][1] = 0; }
        #pragma unroll 2
        for (int f = 0; f < LFN; f += 4) {
            float a[4][4];
            #pragma unroll
            for (int r = 0; r < 4; r++) {
                float4 t = *(const float4*)&sm[LN_OFF + (l0 + r) * 64 + f];
                a[r][0] = t.x; a[r][1] = t.y; a[r][2] = t.z; a[r][3] = t.w;
            }
            #pragma unroll
            for (int j = 0; j < 4; j++) {
                u64 w0 = *(const u64*)&sm[W_OFF + (f + j) * 130 + 2 * lane];
                u64 w1 = *(const u64*)&sm[W_OFF + (f + j) * 130 + 2 * lane + 64];
                #pragma unroll
                for (int r = 0; r < 4; r++) {
                    u64 av = dup2(a[r][j]);
                    acc[r][0] = ffma2(av, w0, acc[r][0]);
                    acc[r][1] = ffma2(av, w1, acc[r][1]);
                }
            }
        }
        #pragma unroll
        for (int c = 0; c < 2; c++)
            #pragma unroll
            for (int r = 0; r < 4; r++) {
                float2 v = unpack2(acc[r][c]);
                *(float2*)&sm[V_OFF + (l0 + r) * FF + 2 * lane + 64 * c] = v;
            }
    }
    __syncthreads();

    // ---------- per-t-half pipeline ----------
    for (int th2 = 0; th2 < 2; th2++) {
        const int tbase = th2 * 16;
        const int tcnt  = (TT - tbase) < 16 ? (TT - tbase) : 16;
        const int tw    = w >> 2;           // 0..3
        const int sub   = w & 3;            // gq for Q/Y, h for attn

        // load X half + Wq half0
        for (int idx = tid; idx < tcnt * FF; idx += NTHR) {
            int tl = idx >> 7, f = idx & 127;
            sm[X_OFF + idx] = veh[(size_t)((tbase + tl) * NBLK + bid) * FF + f];
        }
        load_w66(sm, Wq, 0, tid);
        __syncthreads();

        // -------- Q: f-paired FFMA2; lane col g = lane+32*sub, rows t=tw*4+it --------
        {
            const int g = lane + 32 * sub;
            u64 acc[4] = {0, 0, 0, 0};
            #pragma unroll
            for (int half = 0; half < 2; half++) {
                #pragma unroll 2
                for (int f = 0; f < 64; f += 4) {
                    u64 w01 = *(const u64*)&sm[W_OFF + g * 66 + f];
                    u64 w23 = *(const u64*)&sm[W_OFF + g * 66 + f + 2];
                    #pragma unroll
                    for (int it = 0; it < 4; it++) {
                        ulonglong2 a = *(const ulonglong2*)
                            &sm[X_OFF + (tw * 4 + it) * FF + half * 64 + f];
                        acc[it] = ffma2(a.x, w01, acc[it]);
                        acc[it] = ffma2(a.y, w23, acc[it]);
                    }
                }
                if (half == 0) {
                    __syncthreads();
                    load_w66(sm, Wq, 64, tid);
                    __syncthreads();
                }
            }
            #pragma unroll
            for (int it = 0; it < 4; it++) {
                int tl = tw * 4 + it;
                if (tl < tcnt) {
                    float2 v = unpack2(acc[it]);
                    sm[Q_OFF + tl * FF + g] = v.x + v.y;
                }
            }
        }
        __syncthreads();

        // -------- scores + softmax: warp (h=sub, tw); lane packs (l, l+32) --------
        {
            const int gb = sub * HD;
            u64 acc[4] = {0, 0, 0, 0};   // lo: l=lane, hi: l=lane+32
            #pragma unroll 2
            for (int d = 0; d < HD; d += 4) {
                float qv[4][4];
                #pragma unroll
                for (int it = 0; it < 4; it++) {
                    float4 q = *(const float4*)&sm[Q_OFF + (tw * 4 + it) * FF + gb + d];
                    qv[it][0] = q.x; qv[it][1] = q.y; qv[it][2] = q.z; qv[it][3] = q.w;
                }
                #pragma unroll
                for (int j = 0; j < 4; j++) {
                    float k0 = sm[KT_OFF + (gb + d + j) * 65 + lane];
                    float k1 = sm[KT_OFF + (gb + d + j) * 65 + lane + 32];
                    u64 kk = pack2(k0, k1);
                    #pragma unroll
                    for (int it = 0; it < 4; it++)
                        acc[it] = ffma2(dup2(qv[it][j]), kk, acc[it]);
                }
            }
            const float scale = 0.17677669529663687f; // 1/sqrt(32)
            #pragma unroll
            for (int it = 0; it < 4; it++) {
                int tl = tw * 4 + it;
                if (tl >= tcnt) break;
                float2 sc = unpack2(acc[it]);
                float s0 = km0 ? sc.x * scale : -1e9f;
                float s1 = km1 ? sc.y * scale : -1e9f;
                float m = fmaxf(s0, s1);
                #pragma unroll
                for (int o = 16; o; o >>= 1) m = fmaxf(m, __shfl_xor_sync(0xffffffffu, m, o));
                float e0 = __expf(s0 - m), e1 = __expf(s1 - m);
                float ss = e0 + e1;
                #pragma unroll
                for (int o = 16; o; o >>= 1) ss += __shfl_xor_sync(0xffffffffu, ss, o);
                float inv = 1.0f / ss;
                sm[P_OFF + tl * 256 + sub * 64 + lane]      = e0 * inv;
                sm[P_OFF + tl * 256 + sub * 64 + lane + 32] = e1 * inv;
            }
        }
        __syncthreads();

        // -------- O = P @ V : warp (h=sub, tw); out d = lane --------
        {
            const int gb = sub * HD;
            float oacc[4] = {0, 0, 0, 0};
            #pragma unroll 2
            for (int l = 0; l < LL; l += 4) {
                float v0 = sm[V_OFF + (l + 0) * FF + gb + lane];
                float v1 = sm[V_OFF + (l + 1) * FF + gb + lane];
                float v2 = sm[V_OFF + (l + 2) * FF + gb + lane];
                float v3 = sm[V_OFF + (l + 3) * FF + gb + lane];
                #pragma unroll
                for (int it = 0; it < 4; it++) {
                    float4 p = *(const float4*)&sm[P_OFF + (tw * 4 + it) * 256 + sub * 64 + l];
                    oacc[it] = fmaf(p.x, v0, fmaf(p.y, v1, fmaf(p.z, v2, fmaf(p.w, v3, oacc[it]))));
                }
            }
            #pragma unroll
            for (int it = 0; it < 4; it++)
                if (tw * 4 + it < tcnt)
                    sm[O_OFF + (tw * 4 + it) * FF + gb + lane] = oacc[it];
        }
        __syncthreads();

        // -------- Y = O @ Wc^T + residual --------
        load_w66(sm, Wc, 0, tid);
        __syncthreads();
        {
            const int g = lane + 32 * sub;
            float xv[4];
            #pragma unroll
            for (int it = 0; it < 4; it++) {
                int tl = tw * 4 + it;
                xv[it] = (tl < tcnt)
                    ? veh[(size_t)((tbase + tl) * NBLK + bid) * FF + g] : 0.f;
            }
            u64 acc[4] = {0, 0, 0, 0};
            #pragma unroll
            for (int half = 0; half < 2; half++) {
                #pragma unroll 2
                for (int f = 0; f < 64; f += 4) {
                    u64 w01 = *(const u64*)&sm[W_OFF + g * 66 + f];
                    u64 w23 = *(const u64*)&sm[W_OFF + g * 66 + f + 2];
                    #pragma unroll
                    for (int it = 0; it < 4; it++) {
                        ulonglong2 a = *(const ulonglong2*)
                            &sm[O_OFF + (tw * 4 + it) * FF + half * 64 + f];
                        acc[it] = ffma2(a.x, w01, acc[it]);
                        acc[it] = ffma2(a.y, w23, acc[it]);
                    }
                }
                if (half == 0) {
                    __syncthreads();
                    load_w66(sm, Wc, 64, tid);
                    __syncthreads();
                }
            }
            #pragma unroll
            for (int it = 0; it < 4; it++) {
                int tl = tw * 4 + it;
                if (tl < tcnt) {
                    float2 v = unpack2(acc[it]);
                    out[(size_t)((tbase + tl) * NBLK + bid) * FF + g] = v.x + v.y + xv[it];
                }
            }
        }
        __syncthreads();
    }
}

extern "C" void kernel_launch(void* const* d_in, const int* in_sizes, int n_in,
                              void* d_out, int out_size)
{
    const float* veh   = (const float*)d_in[0];
    const float* lanes = (const float*)d_in[1];
    const int*   maskl = (const int*)d_in[2];
    const float* Wk    = (const float*)d_in[3];
    const float* Wv    = (const float*)d_in[4];
    const float* Wq    = (const float*)d_in[5];
    const float* Wc    = (const float*)d_in[6];

    const size_t smem = SMEM_FLOATS * sizeof(float); // 116224 B
    cudaFuncSetAttribute(lane_attn_kernel,
                         cudaFuncAttributeMaxDynamicSharedMemorySize, (int)smem);
    lane_attn_kernel<<<NBLK, NTHR, smem>>>(veh, lanes, maskl, Wk, Wv, Wq, Wc,
                                           (float*)d_out);
}

// round 5
// speedup vs baseline: 1.3735x; 1.3735x over previous
#include <cuda_runtime.h>

// LaneAttention fused, fp32, sm_103a. 2 CTAs/SM (SMEM = 115712 B exactly).
// R3 layout + FFMA2 (packed f32x2) in K/V and scores phases only.

#define TT   30
#define FF   128
#define LL   64
#define LFN  64
#define NH   4
#define HD   32
#define THN  20
#define NBLK 2048
#define NTHR 512

typedef unsigned long long u64;

// SMEM regions (float offsets) — identical to R3 (483us kernel)
#define KT_OFF 0          // Kt[128 g][65]
#define W_OFF  8320       // weight tile: Wt[f][130] (K/V, 64x130=8320) or W[g][65] (Q/Y)
#define P_OFF  8320       // sP[16][256] overlays W
#define V_OFF  16640      // sV[64 l][128 g]
#define X_OFF  24832      // sX[16][128]; sO overlays; LN[64][64] overlays X+Q
#define O_OFF  24832
#define LN_OFF 24832
#define Q_OFF  26880      // sQ[16][128]
#define SMEM_FLOATS 28928 // 115712 B -> 2 CTAs/SM

__device__ __forceinline__ u64 ffma2(u64 a, u64 b, u64 c) {
    u64 d;
    asm("fma.rn.f32x2 %0, %1, %2, %3;" : "=l"(d) : "l"(a), "l"(b), "l"(c));
    return d;
}
__device__ __forceinline__ u64 dup2(float x) {
    u64 d; asm("mov.b64 %0, {%1, %1};" : "=l"(d) : "f"(x)); return d;
}
__device__ __forceinline__ u64 pack2(float lo, float hi) {
    u64 d; asm("mov.b64 %0, {%1, %2};" : "=l"(d) : "f"(lo), "f"(hi)); return d;
}
__device__ __forceinline__ float2 unpack2(u64 a) {
    float2 r; asm("mov.b64 {%0, %1}, %2;" : "=f"(r.x), "=f"(r.y) : "l"(a)); return r;
}

// Wk/Wv: transposed tile Wt[f][g], stride 130 (even -> per-lane LDS.64 g-pairs)
__device__ __forceinline__ void load_wt(float* sm, const float* Wsrc, int tid) {
    for (int idx = tid; idx < 128 * 64; idx += NTHR) {
        int g = idx >> 6, f = idx & 63;
        sm[W_OFF + f * 130 + g] = Wsrc[g * 64 + f];
    }
}
// Wq/Wc halves: g-major tile W[g][f], stride 65 (R3 layout, scalar reads)
__device__ __forceinline__ void load_w65(float* sm, const float* Wsrc,
                                         int foff, int tid) {
    for (int idx = tid; idx < 128 * 64; idx += NTHR) {
        int g = idx >> 6, f = idx & 63;
        sm[W_OFF + g * 65 + f] = Wsrc[g * FF + foff + f];
    }
}

__global__ void __launch_bounds__(NTHR, 2)
lane_attn_kernel(const float* __restrict__ veh,
                 const float* __restrict__ lanes,
                 const int* __restrict__ maskl,
                 const float* __restrict__ Wk, const float* __restrict__ Wv,
                 const float* __restrict__ Wq, const float* __restrict__ Wc,
                 float* __restrict__ out)
{
    extern __shared__ float sm[];
    const int tid  = threadIdx.x;
    const int w    = tid >> 5;
    const int lane = tid & 31;
    const int bid  = blockIdx.x;

    // ---------- mask in registers ----------
    int mi0 = 0, mi1 = 0;
    #pragma unroll
    for (int th = 0; th < THN; th++) {
        const int* mp = maskl + (size_t)(th * NBLK + bid) * LL;
        mi0 |= mp[lane];
        mi1 |= mp[lane + 32];
    }
    const bool km0 = (mi0 != 0), km1 = (mi1 != 0);

    // ---------- load lanes + Wk^T ----------
    {
        const float* lp = lanes + (size_t)bid * (LL * LFN);
        for (int idx = tid; idx < LL * LFN; idx += NTHR) sm[LN_OFF + idx] = lp[idx];
        load_wt(sm, Wk, tid);
    }
    __syncthreads();

    // ---------- K phase: Kt[g][l], output-paired FFMA2 ----------
    {
        const int l0 = w * 4;
        u64 acc[4][2];
        #pragma unroll
        for (int r = 0; r < 4; r++) { acc[r][0] = 0; acc[r][1] = 0; }
        #pragma unroll 2
        for (int f = 0; f < LFN; f += 4) {
            float a[4][4];
            #pragma unroll
            for (int r = 0; r < 4; r++) {
                float4 t = *(const float4*)&sm[LN_OFF + (l0 + r) * 64 + f];
                a[r][0] = t.x; a[r][1] = t.y; a[r][2] = t.z; a[r][3] = t.w;
            }
            #pragma unroll
            for (int j = 0; j < 4; j++) {
                u64 w0 = *(const u64*)&sm[W_OFF + (f + j) * 130 + 2 * lane];
                u64 w1 = *(const u64*)&sm[W_OFF + (f + j) * 130 + 2 * lane + 64];
                #pragma unroll
                for (int r = 0; r < 4; r++) {
                    u64 av = dup2(a[r][j]);
                    acc[r][0] = ffma2(av, w0, acc[r][0]);
                    acc[r][1] = ffma2(av, w1, acc[r][1]);
                }
            }
        }
        #pragma unroll
        for (int c = 0; c < 2; c++)
            #pragma unroll
            for (int r = 0; r < 4; r++) {
                float2 v = unpack2(acc[r][c]);
                int g = 2 * lane + 64 * c;
                sm[KT_OFF + g       * 65 + l0 + r] = v.x;
                sm[KT_OFF + (g + 1) * 65 + l0 + r] = v.y;
            }
    }
    __syncthreads();
    load_wt(sm, Wv, tid);
    __syncthreads();

    // ---------- V phase: sV[l][g], paired FFMA2 + STS.64 ----------
    {
        const int l0 = w * 4;
        u64 acc[4][2];
        #pragma unroll
        for (int r = 0; r < 4; r++) { acc[r][0] = 0; acc[r][1] = 0; }
        #pragma unroll 2
        for (int f = 0; f < LFN; f += 4) {
            float a[4][4];
            #pragma unroll
            for (int r = 0; r < 4; r++) {
                float4 t = *(const float4*)&sm[LN_OFF + (l0 + r) * 64 + f];
                a[r][0] = t.x; a[r][1] = t.y; a[r][2] = t.z; a[r][3] = t.w;
            }
            #pragma unroll
            for (int j = 0; j < 4; j++) {
                u64 w0 = *(const u64*)&sm[W_OFF + (f + j) * 130 + 2 * lane];
                u64 w1 = *(const u64*)&sm[W_OFF + (f + j) * 130 + 2 * lane + 64];
                #pragma unroll
                for (int r = 0; r < 4; r++) {
                    u64 av = dup2(a[r][j]);
                    acc[r][0] = ffma2(av, w0, acc[r][0]);
                    acc[r][1] = ffma2(av, w1, acc[r][1]);
                }
            }
        }
        #pragma unroll
        for (int c = 0; c < 2; c++)
            #pragma unroll
            for (int r = 0; r < 4; r++) {
                float2 v = unpack2(acc[r][c]);
                *(float2*)&sm[V_OFF + (l0 + r) * FF + 2 * lane + 64 * c] = v;
            }
    }
    __syncthreads();

    // ---------- per-t-half pipeline ----------
    for (int th2 = 0; th2 < 2; th2++) {
        const int tbase = th2 * 16;
        const int tcnt  = (TT - tbase) < 16 ? (TT - tbase) : 16;
        const int tw    = w >> 2;   // 0..3
        const int sub   = w & 3;    // gq for Q/Y, h for attn

        // load X half + Wq half0
        for (int idx = tid; idx < tcnt * FF; idx += NTHR) {
            int tl = idx >> 7, f = idx & 127;
            sm[X_OFF + idx] = veh[(size_t)((tbase + tl) * NBLK + bid) * FF + f];
        }
        load_w65(sm, Wq, 0, tid);
        __syncthreads();

        // -------- Q (R3 code): scalar weights, float4 operand --------
        {
            const int g = lane + 32 * sub;
            float acc[4] = {0.f, 0.f, 0.f, 0.f};
            #pragma unroll
            for (int half = 0; half < 2; half++) {
                #pragma unroll 2
                for (int f = 0; f < 64; f += 4) {
                    const float* wp = &sm[W_OFF + g * 65 + f];
                    float w0 = wp[0], w1 = wp[1], w2 = wp[2], w3 = wp[3];
                    #pragma unroll
                    for (int it = 0; it < 4; it++) {
                        float4 a = *(const float4*)&sm[X_OFF + (tw*4+it)*FF + half*64 + f];
                        acc[it] = fmaf(a.x,w0, fmaf(a.y,w1, fmaf(a.z,w2, fmaf(a.w,w3, acc[it]))));
                    }
                }
                if (half == 0) {
                    __syncthreads();
                    load_w65(sm, Wq, 64, tid);
                    __syncthreads();
                }
            }
            #pragma unroll
            for (int it = 0; it < 4; it++)
                if (tw*4 + it < tcnt)
                    sm[Q_OFF + (tw*4+it)*FF + g] = acc[it];
        }
        __syncthreads();

        // -------- scores + softmax: FFMA2, lane packs (l, l+32) --------
        {
            const int gb = sub * HD;
            u64 acc[4] = {0, 0, 0, 0};
            #pragma unroll 2
            for (int d = 0; d < HD; d += 4) {
                float qv[4][4];
                #pragma unroll
                for (int it = 0; it < 4; it++) {
                    float4 q = *(const float4*)&sm[Q_OFF + (tw * 4 + it) * FF + gb + d];
                    qv[it][0] = q.x; qv[it][1] = q.y; qv[it][2] = q.z; qv[it][3] = q.w;
                }
                #pragma unroll
                for (int j = 0; j < 4; j++) {
                    float k0 = sm[KT_OFF + (gb + d + j) * 65 + lane];
                    float k1 = sm[KT_OFF + (gb + d + j) * 65 + lane + 32];
                    u64 kk = pack2(k0, k1);
                    #pragma unroll
                    for (int it = 0; it < 4; it++)
                        acc[it] = ffma2(dup2(qv[it][j]), kk, acc[it]);
                }
            }
            const float scale = 0.17677669529663687f; // 1/sqrt(32)
            #pragma unroll
            for (int it = 0; it < 4; it++) {
                int tl = tw * 4 + it;
                if (tl >= tcnt) break;
                float2 sc = unpack2(acc[it]);
                float s0 = km0 ? sc.x * scale : -1e9f;
                float s1 = km1 ? sc.y * scale : -1e9f;
                float m = fmaxf(s0, s1);
                #pragma unroll
                for (int o = 16; o; o >>= 1) m = fmaxf(m, __shfl_xor_sync(0xffffffffu, m, o));
                float e0 = __expf(s0 - m), e1 = __expf(s1 - m);
                float ss = e0 + e1;
                #pragma unroll
                for (int o = 16; o; o >>= 1) ss += __shfl_xor_sync(0xffffffffu, ss, o);
                float inv = 1.0f / ss;
                sm[P_OFF + tl * 256 + sub * 64 + lane]      = e0 * inv;
                sm[P_OFF + tl * 256 + sub * 64 + lane + 32] = e1 * inv;
            }
        }
        __syncthreads();

        // -------- O = P @ V (R3 code) --------
        {
            const int gb = sub * HD;
            float oacc[4] = {0, 0, 0, 0};
            #pragma unroll 2
            for (int l = 0; l < LL; l += 4) {
                float v0 = sm[V_OFF + (l + 0) * FF + gb + lane];
                float v1 = sm[V_OFF + (l + 1) * FF + gb + lane];
                float v2 = sm[V_OFF + (l + 2) * FF + gb + lane];
                float v3 = sm[V_OFF + (l + 3) * FF + gb + lane];
                #pragma unroll
                for (int it = 0; it < 4; it++) {
                    float4 p = *(const float4*)&sm[P_OFF + (tw*4+it)*256 + sub*64 + l];
                    oacc[it] = fmaf(p.x,v0, fmaf(p.y,v1, fmaf(p.z,v2, fmaf(p.w,v3, oacc[it]))));
                }
            }
            #pragma unroll
            for (int it = 0; it < 4; it++)
                if (tw*4 + it < tcnt)
                    sm[O_OFF + (tw*4+it)*FF + gb + lane] = oacc[it];
        }
        __syncthreads();

        // -------- Y = O @ Wc^T + residual (R3 code) --------
        load_w65(sm, Wc, 0, tid);
        __syncthreads();
        {
            const int g = lane + 32 * sub;
            float xv[4];
            #pragma unroll
            for (int it = 0; it < 4; it++) {
                int tl = tw*4 + it;
                xv[it] = (tl < tcnt)
                    ? veh[(size_t)((tbase + tl) * NBLK + bid) * FF + g] : 0.f;
            }
            float acc[4] = {0.f, 0.f, 0.f, 0.f};
            #pragma unroll
            for (int half = 0; half < 2; half++) {
                #pragma unroll 2
                for (int f = 0; f < 64; f += 4) {
                    const float* wp = &sm[W_OFF + g * 65 + f];
                    float w0 = wp[0], w1 = wp[1], w2 = wp[2], w3 = wp[3];
                    #pragma unroll
                    for (int it = 0; it < 4; it++) {
                        float4 a = *(const float4*)&sm[O_OFF + (tw*4+it)*FF + half*64 + f];
                        acc[it] = fmaf(a.x,w0, fmaf(a.y,w1, fmaf(a.z,w2, fmaf(a.w,w3, acc[it]))));
                    }
                }
                if (half == 0) {
                    __syncthreads();
                    load_w65(sm, Wc, 64, tid);
                    __syncthreads();
                }
            }
            #pragma unroll
            for (int it = 0; it < 4; it++) {
                int tl = tw*4 + it;
                if (tl < tcnt)
                    out[(size_t)((tbase + tl) * NBLK + bid) * FF + g] = acc[it] + xv[it];
            }
        }
        __syncthreads();
    }
}

extern "C" void kernel_launch(void* const* d_in, const int* in_sizes, int n_in,
                              void* d_out, int out_size)
{
    const float* veh   = (const float*)d_in[0];
    const float* lanes = (const float*)d_in[1];
    const int*   maskl = (const int*)d_in[2];
    const float* Wk    = (const float*)d_in[3];
    const float* Wv    = (const float*)d_in[4];
    const float* Wq    = (const float*)d_in[5];
    const float* Wc    = (const float*)d_in[6];

    const size_t smem = SMEM_FLOATS * sizeof(float); // 115712 B
    cudaFuncSetAttribute(lane_attn_kernel,
                         cudaFuncAttributeMaxDynamicSharedMemorySize, (int)smem);
    lane_attn_kernel<<<NBLK, NTHR, smem>>>(veh, lanes, maskl, Wk, Wv, Wq, Wc,
                                           (float*)d_out);
}

// round 6
// speedup vs baseline: 1.4712x; 1.0711x over previous
#include <cuda_runtime.h>

// LaneAttention fused, fp32, sm_103a. 2 CTAs/SM (SMEM = 115712 B exactly).
// Full-t (30) tiles: Q/scores/O/Y in one pass, t-tile=8 per warp.
// FFMA2 in K/V (output-paired), scores (l-paired), Q/Y (f-paired).

#define TT   30
#define FF   128
#define LL   64
#define LFN  64
#define NH   4
#define HD   32
#define THN  20
#define NBLK 2048
#define NTHR 512

typedef unsigned long long u64;

// ---- SMEM layout (float offsets), total 28928 floats = 115712 B ----
#define KT_OFF 0       // Kt[128 g][65]; O[30][132] overlays after scores
#define O_OFF  0
#define V_OFF  8320    // sV[64 l][128 g]
#define QF_OFF 16512   // Q[30][132]; LN[64][64] overlays during K/V
#define LN_OFF 16512
#define XF_OFF 20472   // X[30][128] (Q phase); P[30][256] overlays (scores/O)
#define P_OFF  20472
#define WT_OFF 20608   // Wt[64 f][130] (K/V weight tile, 8320)
#define WQ_OFF 24312   // W quarter [128 g][34] (Q/Y), 4352
#define SMEM_FLOATS 28928

__device__ __forceinline__ u64 ffma2(u64 a, u64 b, u64 c) {
    u64 d;
    asm("fma.rn.f32x2 %0, %1, %2, %3;" : "=l"(d) : "l"(a), "l"(b), "l"(c));
    return d;
}
__device__ __forceinline__ u64 dup2(float x) {
    u64 d; asm("mov.b64 %0, {%1, %1};" : "=l"(d) : "f"(x)); return d;
}
__device__ __forceinline__ u64 pack2(float lo, float hi) {
    u64 d; asm("mov.b64 %0, {%1, %2};" : "=l"(d) : "f"(lo), "f"(hi)); return d;
}
__device__ __forceinline__ float2 unpack2(u64 a) {
    float2 r; asm("mov.b64 {%0, %1}, %2;" : "=f"(r.x), "=f"(r.y) : "l"(a)); return r;
}

// Wk/Wv: transposed tile Wt[f][g], stride 130 (per-lane LDS.64 g-pairs)
__device__ __forceinline__ void load_wt(float* sm, const float* Wsrc, int tid) {
    for (int idx = tid; idx < 128 * 64; idx += NTHR) {
        int g = idx >> 6, f = idx & 63;
        sm[WT_OFF + f * 130 + g] = Wsrc[g * 64 + f];
    }
}
// Wq/Wc f-quarter: W[g][fi], stride 34 (8B-aligned f-pair LDS.64)
__device__ __forceinline__ void load_wq(float* sm, const float* Wsrc,
                                        int fq, int tid) {
    for (int idx = tid; idx < 128 * 32; idx += NTHR) {
        int g = idx >> 5, fi = idx & 31;
        sm[WQ_OFF + g * 34 + fi] = Wsrc[g * FF + fq * 32 + fi];
    }
}

__global__ void __launch_bounds__(NTHR, 2)
lane_attn_kernel(const float* __restrict__ veh,
                 const float* __restrict__ lanes,
                 const int* __restrict__ maskl,
                 const float* __restrict__ Wk, const float* __restrict__ Wv,
                 const float* __restrict__ Wq, const float* __restrict__ Wc,
                 float* __restrict__ out)
{
    extern __shared__ float sm[];
    const int tid  = threadIdx.x;
    const int w    = tid >> 5;
    const int lane = tid & 31;
    const int bid  = blockIdx.x;
    const int tw   = w >> 2;      // t-group (8 t each)
    const int sub  = w & 3;       // g-group for Q/Y, head for attn

    // ---------- mask in registers ----------
    int mi0 = 0, mi1 = 0;
    #pragma unroll
    for (int th = 0; th < THN; th++) {
        const int* mp = maskl + (size_t)(th * NBLK + bid) * LL;
        mi0 |= mp[lane];
        mi1 |= mp[lane + 32];
    }
    const bool km0 = (mi0 != 0), km1 = (mi1 != 0);

    // ---------- load lanes + Wk^T ----------
    {
        const float* lp = lanes + (size_t)bid * (LL * LFN);
        for (int idx = tid; idx < LL * LFN; idx += NTHR) sm[LN_OFF + idx] = lp[idx];
        load_wt(sm, Wk, tid);
    }
    __syncthreads();

    // ---------- K phase: Kt[g][l], output-paired FFMA2 (R5 code) ----------
    {
        const int l0 = w * 4;
        u64 acc[4][2];
        #pragma unroll
        for (int r = 0; r < 4; r++) { acc[r][0] = 0; acc[r][1] = 0; }
        #pragma unroll 2
        for (int f = 0; f < LFN; f += 4) {
            float a[4][4];
            #pragma unroll
            for (int r = 0; r < 4; r++) {
                float4 t = *(const float4*)&sm[LN_OFF + (l0 + r) * 64 + f];
                a[r][0] = t.x; a[r][1] = t.y; a[r][2] = t.z; a[r][3] = t.w;
            }
            #pragma unroll
            for (int j = 0; j < 4; j++) {
                u64 w0 = *(const u64*)&sm[WT_OFF + (f + j) * 130 + 2 * lane];
                u64 w1 = *(const u64*)&sm[WT_OFF + (f + j) * 130 + 2 * lane + 64];
                #pragma unroll
                for (int r = 0; r < 4; r++) {
                    u64 av = dup2(a[r][j]);
                    acc[r][0] = ffma2(av, w0, acc[r][0]);
                    acc[r][1] = ffma2(av, w1, acc[r][1]);
                }
            }
        }
        #pragma unroll
        for (int c = 0; c < 2; c++)
            #pragma unroll
            for (int r = 0; r < 4; r++) {
                float2 v = unpack2(acc[r][c]);
                int g = 2 * lane + 64 * c;
                sm[KT_OFF + g       * 65 + l0 + r] = v.x;
                sm[KT_OFF + (g + 1) * 65 + l0 + r] = v.y;
            }
    }
    __syncthreads();
    load_wt(sm, Wv, tid);
    __syncthreads();

    // ---------- V phase: sV[l][g] (R5 code) ----------
    {
        const int l0 = w * 4;
        u64 acc[4][2];
        #pragma unroll
        for (int r = 0; r < 4; r++) { acc[r][0] = 0; acc[r][1] = 0; }
        #pragma unroll 2
        for (int f = 0; f < LFN; f += 4) {
            float a[4][4];
            #pragma unroll
            for (int r = 0; r < 4; r++) {
                float4 t = *(const float4*)&sm[LN_OFF + (l0 + r) * 64 + f];
                a[r][0] = t.x; a[r][1] = t.y; a[r][2] = t.z; a[r][3] = t.w;
            }
            #pragma unroll
            for (int j = 0; j < 4; j++) {
                u64 w0 = *(const u64*)&sm[WT_OFF + (f + j) * 130 + 2 * lane];
                u64 w1 = *(const u64*)&sm[WT_OFF + (f + j) * 130 + 2 * lane + 64];
                #pragma unroll
                for (int r = 0; r < 4; r++) {
                    u64 av = dup2(a[r][j]);
                    acc[r][0] = ffma2(av, w0, acc[r][0]);
                    acc[r][1] = ffma2(av, w1, acc[r][1]);
                }
            }
        }
        #pragma unroll
        for (int c = 0; c < 2; c++)
            #pragma unroll
            for (int r = 0; r < 4; r++) {
                float2 v = unpack2(acc[r][c]);
                *(float2*)&sm[V_OFF + (l0 + r) * FF + 2 * lane + 64 * c] = v;
            }
    }
    __syncthreads();   // LN/WT regions now free

    // ---------- Q phase: full t, f-quarter weights, f-paired FFMA2 ----------
    {
        // load full X [30][128]
        for (int idx = tid; idx < TT * FF; idx += NTHR) {
            int t = idx >> 7, f = idx & 127;
            sm[XF_OFF + idx] = veh[(size_t)(t * NBLK + bid) * FF + f];
        }
        load_wq(sm, Wq, 0, tid);
        __syncthreads();

        const int g = lane + 32 * sub;
        u64 qacc[8] = {0,0,0,0,0,0,0,0};
        #pragma unroll
        for (int fq = 0; fq < 4; fq++) {
            #pragma unroll 2
            for (int f8 = 0; f8 < 32; f8 += 4) {
                u64 w01 = *(const u64*)&sm[WQ_OFF + g * 34 + f8];
                u64 w23 = *(const u64*)&sm[WQ_OFF + g * 34 + f8 + 2];
                #pragma unroll
                for (int it = 0; it < 8; it++) {
                    int tr = tw * 8 + it; tr = tr < TT ? tr : (TT - 1);
                    ulonglong2 a = *(const ulonglong2*)
                        &sm[XF_OFF + tr * FF + fq * 32 + f8];
                    qacc[it] = ffma2(a.x, w01, qacc[it]);
                    qacc[it] = ffma2(a.y, w23, qacc[it]);
                }
            }
            if (fq < 3) {
                __syncthreads();
                load_wq(sm, Wq, fq + 1, tid);
                __syncthreads();
            }
        }
        #pragma unroll
        for (int it = 0; it < 8; it++) {
            int t = tw * 8 + it;
            if (t < TT) {
                float2 v = unpack2(qacc[it]);
                sm[QF_OFF + t * 132 + g] = v.x + v.y;
            }
        }
    }
    __syncthreads();

    // ---------- scores + softmax: warp (h=sub, tw), 8 t; FFMA2 over (l,l+32) ----------
    {
        const int gb = sub * HD;
        u64 acc[8] = {0,0,0,0,0,0,0,0};
        #pragma unroll 2
        for (int d = 0; d < HD; d += 4) {
            u64 kk[4];
            #pragma unroll
            for (int j = 0; j < 4; j++) {
                float k0 = sm[KT_OFF + (gb + d + j) * 65 + lane];
                float k1 = sm[KT_OFF + (gb + d + j) * 65 + lane + 32];
                kk[j] = pack2(k0, k1);
            }
            #pragma unroll
            for (int it = 0; it < 8; it++) {
                int tr = tw * 8 + it; tr = tr < TT ? tr : (TT - 1);
                float4 q = *(const float4*)&sm[QF_OFF + tr * 132 + gb + d];
                acc[it] = ffma2(dup2(q.x), kk[0], acc[it]);
                acc[it] = ffma2(dup2(q.y), kk[1], acc[it]);
                acc[it] = ffma2(dup2(q.z), kk[2], acc[it]);
                acc[it] = ffma2(dup2(q.w), kk[3], acc[it]);
            }
        }
        const float scale = 0.17677669529663687f; // 1/sqrt(32)
        #pragma unroll
        for (int it = 0; it < 8; it++) {
            int t = tw * 8 + it;
            if (t >= TT) break;
            float2 sc = unpack2(acc[it]);
            float s0 = km0 ? sc.x * scale : -1e9f;
            float s1 = km1 ? sc.y * scale : -1e9f;
            float m = fmaxf(s0, s1);
            #pragma unroll
            for (int o = 16; o; o >>= 1) m = fmaxf(m, __shfl_xor_sync(0xffffffffu, m, o));
            float e0 = __expf(s0 - m), e1 = __expf(s1 - m);
            float ss = e0 + e1;
            #pragma unroll
            for (int o = 16; o; o >>= 1) ss += __shfl_xor_sync(0xffffffffu, ss, o);
            float inv = 1.0f / ss;
            sm[P_OFF + t * 256 + sub * 64 + lane]      = e0 * inv;
            sm[P_OFF + t * 256 + sub * 64 + lane + 32] = e1 * inv;
        }
    }
    __syncthreads();   // KT now dead -> O overlays it

    // ---------- O = P @ V : warp (h=sub, tw), 8 t; out d = lane ----------
    {
        const int gb = sub * HD;
        float oacc[8] = {0,0,0,0,0,0,0,0};
        #pragma unroll 2
        for (int l = 0; l < LL; l += 4) {
            float v0 = sm[V_OFF + (l + 0) * FF + gb + lane];
            float v1 = sm[V_OFF + (l + 1) * FF + gb + lane];
            float v2 = sm[V_OFF + (l + 2) * FF + gb + lane];
            float v3 = sm[V_OFF + (l + 3) * FF + gb + lane];
            #pragma unroll
            for (int it = 0; it < 8; it++) {
                int tr = tw * 8 + it; tr = tr < TT ? tr : (TT - 1);
                float4 p = *(const float4*)&sm[P_OFF + tr * 256 + sub * 64 + l];
                oacc[it] = fmaf(p.x, v0, fmaf(p.y, v1, fmaf(p.z, v2, fmaf(p.w, v3, oacc[it]))));
            }
        }
        #pragma unroll
        for (int it = 0; it < 8; it++) {
            int t = tw * 8 + it;
            if (t < TT)
                sm[O_OFF + t * 132 + gb + lane] = oacc[it];
        }
    }
    __syncthreads();   // P now dead -> WQ overlays it

    // ---------- Y = O @ Wc^T + residual, f-paired FFMA2, coalesced STG ----------
    {
        load_wq(sm, Wc, 0, tid);
        __syncthreads();

        const int g = lane + 32 * sub;
        u64 yacc[8] = {0,0,0,0,0,0,0,0};
        #pragma unroll
        for (int fq = 0; fq < 4; fq++) {
            #pragma unroll 2
            for (int f8 = 0; f8 < 32; f8 += 4) {
                u64 w01 = *(const u64*)&sm[WQ_OFF + g * 34 + f8];
                u64 w23 = *(const u64*)&sm[WQ_OFF + g * 34 + f8 + 2];
                #pragma unroll
                for (int it = 0; it < 8; it++) {
                    int tr = tw * 8 + it; tr = tr < TT ? tr : (TT - 1);
                    ulonglong2 a = *(const ulonglong2*)
                        &sm[O_OFF + tr * 132 + fq * 32 + f8];
                    yacc[it] = ffma2(a.x, w01, yacc[it]);
                    yacc[it] = ffma2(a.y, w23, yacc[it]);
                }
            }
            if (fq < 3) {
                __syncthreads();
                load_wq(sm, Wc, fq + 1, tid);
                __syncthreads();
            }
        }
        #pragma unroll
        for (int it = 0; it < 8; it++) {
            int t = tw * 8 + it;
            if (t < TT) {
                float2 v = unpack2(yacc[it]);
                size_t o = (size_t)(t * NBLK + bid) * FF + g;
                out[o] = v.x + v.y + veh[o];
            }
        }
    }
}

extern "C" void kernel_launch(void* const* d_in, const int* in_sizes, int n_in,
                              void* d_out, int out_size)
{
    const float* veh   = (const float*)d_in[0];
    const float* lanes = (const float*)d_in[1];
    const int*   maskl = (const int*)d_in[2];
    const float* Wk    = (const float*)d_in[3];
    const float* Wv    = (const float*)d_in[4];
    const float* Wq    = (const float*)d_in[5];
    const float* Wc    = (const float*)d_in[6];

    const size_t smem = SMEM_FLOATS * sizeof(float); // 115712 B
    cudaFuncSetAttribute(lane_attn_kernel,
                         cudaFuncAttributeMaxDynamicSharedMemorySize, (int)smem);
    lane_attn_kernel<<<NBLK, NTHR, smem>>>(veh, lanes, maskl, Wk, Wv, Wq, Wc,
                                           (float*)d_out);
}

// round 7
// speedup vs baseline: 1.5429x; 1.0487x over previous
#include <cuda_runtime.h>

// LaneAttention fused, fp32 + f32x2, sm_103a. 2 CTAs/SM (115712 B).
// Phase order: Q -> K -> V -> scores -> O -> Y.
// Q/Y: output-paired FFMA2, f-split across warps, f32x2 reduce.
// K/V: 8-row x 1-g-pair tiling, transposed half-tiles.

#define TT   30
#define FF   128
#define LL   64
#define LFN  64
#define THN  20
#define NBLK 2048
#define NTHR 512

typedef unsigned long long u64;

// ---- SMEM float offsets (regions reused across phases) ----
#define WQ2_OFF 0      // Q/Y weight: two transposed quarter tiles [32][130] (+0, +4160)
#define KT_OFF  0      // K..scores: Kt[128 g][65]
#define PB_OFF  8320   // Q/Y reduce partials: [30 t][64 pair] u64 = 3840 floats
#define V_OFF   8320   // K/V..O: V[64 l][128 g]
#define QD_OFF  16512  // Q[30][132] (Q..scores); O[30][132] (O..Y)
#define OD_OFF  16512
#define X_OFF   20472  // X[30][128] during Q
#define LN_OFF  20472  // lanes[64][64] during K/V
#define WC2_OFF 20472  // Y weight tiles (8320)
#define P_OFF   20608  // P[30][256] scores..O
#define WT_OFF  24568  // K/V weight half tile [32][130]
#define SMEM_FLOATS 28928   // 115712 B

__device__ __forceinline__ u64 ffma2(u64 a, u64 b, u64 c) {
    u64 d;
    asm("fma.rn.f32x2 %0, %1, %2, %3;" : "=l"(d) : "l"(a), "l"(b), "l"(c));
    return d;
}
__device__ __forceinline__ u64 addf2(u64 a, u64 b) {
    u64 d;
    asm("add.rn.f32x2 %0, %1, %2;" : "=l"(d) : "l"(a), "l"(b));
    return d;
}
__device__ __forceinline__ u64 dup2(float x) {
    u64 d; asm("mov.b64 %0, {%1, %1};" : "=l"(d) : "f"(x)); return d;
}
__device__ __forceinline__ u64 pack2(float lo, float hi) {
    u64 d; asm("mov.b64 %0, {%1, %2};" : "=l"(d) : "f"(lo), "f"(hi)); return d;
}
__device__ __forceinline__ float2 unpack2(u64 a) {
    float2 r; asm("mov.b64 {%0, %1}, %2;" : "=f"(r.x), "=f"(r.y) : "l"(a)); return r;
}

// Q/Y weight stage: two transposed quarter tiles.
// tile 0 -> f in [stage*32, stage*32+32)          (for fh=0 warps)
// tile 1 -> f in [64+stage*32, 64+stage*32+32)    (for fh=1 warps)
__device__ __forceinline__ void load_wpair2(float* sm, int base, const float* Wsrc,
                                            int stage, int tid) {
    for (int idx = tid; idx < 8192; idx += NTHR) {
        int tile = idx >> 12;
        int rem  = idx & 4095;
        int g    = rem >> 5;
        int fi   = rem & 31;
        sm[base + tile * 4160 + fi * 130 + g] =
            Wsrc[g * FF + tile * 64 + stage * 32 + fi];
    }
}
// K/V weight half tile: transposed [fi][g], f in [half*32, half*32+32)
__device__ __forceinline__ void load_wthalf(float* sm, const float* Wsrc,
                                            int half, int tid) {
    for (int idx = tid; idx < 4096; idx += NTHR) {
        int g = idx >> 5, fi = idx & 31;
        sm[WT_OFF + fi * 130 + g] = Wsrc[g * LFN + half * 32 + fi];
    }
}

__global__ void __launch_bounds__(NTHR, 2)
lane_attn_kernel(const float* __restrict__ veh,
                 const float* __restrict__ lanes,
                 const int* __restrict__ maskl,
                 const float* __restrict__ Wk, const float* __restrict__ Wv,
                 const float* __restrict__ Wq, const float* __restrict__ Wc,
                 float* __restrict__ out)
{
    extern __shared__ float sm[];
    const int tid  = threadIdx.x;
    const int w    = tid >> 5;
    const int lane = tid & 31;
    const int bid  = blockIdx.x;

    // Q/Y warp roles
    const int fh   = w >> 3;          // f-half
    const int gsub = (w >> 2) & 1;    // g 64-half
    const int tw   = w & 3;           // t-group of 8
    const int gp   = 2 * lane + 64 * gsub;   // owned g-pair base (even)
    // attention warp roles
    const int ah  = w & 3;            // head
    const int atw = w >> 2;           // t-group of 8
    // K/V warp roles
    const int lg  = w >> 1;           // 8 l-rows group
    const int gh  = w & 1;            // g 64-half
    const int kgp = 2 * lane + 64 * gh;

    // ---------- mask in registers ----------
    int mi0 = 0, mi1 = 0;
    #pragma unroll
    for (int th = 0; th < THN; th++) {
        const int* mp = maskl + (size_t)(th * NBLK + bid) * LL;
        mi0 |= mp[lane];
        mi1 |= mp[lane + 32];
    }
    const bool km0 = (mi0 != 0), km1 = (mi1 != 0);

    // ================= Q phase =================
    {
        for (int idx = tid; idx < TT * FF; idx += NTHR) {
            int t = idx >> 7, f = idx & 127;
            sm[X_OFF + idx] = veh[(size_t)(t * NBLK + bid) * FF + f];
        }
        load_wpair2(sm, WQ2_OFF, Wq, 0, tid);
        __syncthreads();

        u64 acc[8] = {0,0,0,0,0,0,0,0};
        const int wbase = WQ2_OFF + fh * 4160;
        #pragma unroll
        for (int stage = 0; stage < 2; stage++) {
            const int fbase = fh * 64 + stage * 32;
            #pragma unroll 2
            for (int f4 = 0; f4 < 32; f4 += 4) {
                u64 w0 = *(const u64*)&sm[wbase + (f4 + 0) * 130 + gp];
                u64 w1 = *(const u64*)&sm[wbase + (f4 + 1) * 130 + gp];
                u64 w2 = *(const u64*)&sm[wbase + (f4 + 2) * 130 + gp];
                u64 w3 = *(const u64*)&sm[wbase + (f4 + 3) * 130 + gp];
                #pragma unroll
                for (int it = 0; it < 8; it++) {
                    int tr = tw * 8 + it; tr = tr < TT ? tr : (TT - 1);
                    float4 a = *(const float4*)&sm[X_OFF + tr * FF + fbase + f4];
                    acc[it] = ffma2(dup2(a.x), w0, acc[it]);
                    acc[it] = ffma2(dup2(a.y), w1, acc[it]);
                    acc[it] = ffma2(dup2(a.z), w2, acc[it]);
                    acc[it] = ffma2(dup2(a.w), w3, acc[it]);
                }
            }
            if (stage == 0) {
                __syncthreads();
                load_wpair2(sm, WQ2_OFF, Wq, 1, tid);
                __syncthreads();
            }
        }
        // reduce f-halves: fh1 stores partial pairs, fh0 combines
        if (fh == 1) {
            #pragma unroll
            for (int it = 0; it < 8; it++) {
                int t = tw * 8 + it;
                if (t < TT)
                    *(u64*)&sm[PB_OFF + (t * 64 + lane + 32 * gsub) * 2] = acc[it];
            }
        }
        __syncthreads();
        if (fh == 0) {
            #pragma unroll
            for (int it = 0; it < 8; it++) {
                int t = tw * 8 + it;
                if (t < TT) {
                    u64 part = *(const u64*)&sm[PB_OFF + (t * 64 + lane + 32 * gsub) * 2];
                    float2 v = unpack2(addf2(acc[it], part));
                    *(float2*)&sm[QD_OFF + t * 132 + gp] = v;
                }
            }
        }
        __syncthreads();
    }

    // ================= K phase =================
    {
        for (int idx = tid; idx < LL * LFN; idx += NTHR)
            sm[LN_OFF + idx] = lanes[(size_t)bid * (LL * LFN) + idx];
        load_wthalf(sm, Wk, 0, tid);
        __syncthreads();

        u64 acc[8] = {0,0,0,0,0,0,0,0};
        const int l0 = lg * 8;
        #pragma unroll
        for (int half = 0; half < 2; half++) {
            #pragma unroll 2
            for (int f4 = 0; f4 < 32; f4 += 4) {
                u64 w0 = *(const u64*)&sm[WT_OFF + (f4 + 0) * 130 + kgp];
                u64 w1 = *(const u64*)&sm[WT_OFF + (f4 + 1) * 130 + kgp];
                u64 w2 = *(const u64*)&sm[WT_OFF + (f4 + 2) * 130 + kgp];
                u64 w3 = *(const u64*)&sm[WT_OFF + (f4 + 3) * 130 + kgp];
                #pragma unroll
                for (int r = 0; r < 8; r++) {
                    float4 a = *(const float4*)&sm[LN_OFF + (l0 + r) * 64 + half * 32 + f4];
                    acc[r] = ffma2(dup2(a.x), w0, acc[r]);
                    acc[r] = ffma2(dup2(a.y), w1, acc[r]);
                    acc[r] = ffma2(dup2(a.z), w2, acc[r]);
                    acc[r] = ffma2(dup2(a.w), w3, acc[r]);
                }
            }
            if (half == 0) {
                __syncthreads();
                load_wthalf(sm, Wk, 1, tid);
                __syncthreads();
            }
        }
        __syncthreads();   // Kt dest overlays dead WQ2; all reads of WQ2 done
        #pragma unroll
        for (int r = 0; r < 8; r++) {
            float2 v = unpack2(acc[r]);
            sm[KT_OFF + kgp       * 65 + l0 + r] = v.x;
            sm[KT_OFF + (kgp + 1) * 65 + l0 + r] = v.y;
        }
    }
    __syncthreads();

    // ================= V phase =================
    {
        load_wthalf(sm, Wv, 0, tid);
        __syncthreads();

        u64 acc[8] = {0,0,0,0,0,0,0,0};
        const int l0 = lg * 8;
        #pragma unroll
        for (int half = 0; half < 2; half++) {
            #pragma unroll 2
            for (int f4 = 0; f4 < 32; f4 += 4) {
                u64 w0 = *(const u64*)&sm[WT_OFF + (f4 + 0) * 130 + kgp];
                u64 w1 = *(const u64*)&sm[WT_OFF + (f4 + 1) * 130 + kgp];
                u64 w2 = *(const u64*)&sm[WT_OFF + (f4 + 2) * 130 + kgp];
                u64 w3 = *(const u64*)&sm[WT_OFF + (f4 + 3) * 130 + kgp];
                #pragma unroll
                for (int r = 0; r < 8; r++) {
                    float4 a = *(const float4*)&sm[LN_OFF + (l0 + r) * 64 + half * 32 + f4];
                    acc[r] = ffma2(dup2(a.x), w0, acc[r]);
                    acc[r] = ffma2(dup2(a.y), w1, acc[r]);
                    acc[r] = ffma2(dup2(a.z), w2, acc[r]);
                    acc[r] = ffma2(dup2(a.w), w3, acc[r]);
                }
            }
            if (half == 0) {
                __syncthreads();
                load_wthalf(sm, Wv, 1, tid);
                __syncthreads();
            }
        }
        #pragma unroll
        for (int r = 0; r < 8; r++) {
            float2 v = unpack2(acc[r]);
            *(float2*)&sm[V_OFF + (l0 + r) * FF + kgp] = v;
        }
    }
    __syncthreads();

    // ================= scores + softmax -> P =================
    {
        const int gb = ah * 32;
        u64 acc[8] = {0,0,0,0,0,0,0,0};
        #pragma unroll 2
        for (int d = 0; d < 32; d += 4) {
            u64 kk[4];
            #pragma unroll
            for (int j = 0; j < 4; j++) {
                float k0 = sm[KT_OFF + (gb + d + j) * 65 + lane];
                float k1 = sm[KT_OFF + (gb + d + j) * 65 + lane + 32];
                kk[j] = pack2(k0, k1);
            }
            #pragma unroll
            for (int it = 0; it < 8; it++) {
                int tr = atw * 8 + it; tr = tr < TT ? tr : (TT - 1);
                float4 q = *(const float4*)&sm[QD_OFF + tr * 132 + gb + d];
                acc[it] = ffma2(dup2(q.x), kk[0], acc[it]);
                acc[it] = ffma2(dup2(q.y), kk[1], acc[it]);
                acc[it] = ffma2(dup2(q.z), kk[2], acc[it]);
                acc[it] = ffma2(dup2(q.w), kk[3], acc[it]);
            }
        }
        const float scale = 0.17677669529663687f; // 1/sqrt(32)
        #pragma unroll
        for (int it = 0; it < 8; it++) {
            int t = atw * 8 + it;
            if (t >= TT) break;
            float2 sc = unpack2(acc[it]);
            float s0 = km0 ? sc.x * scale : -1e9f;
            float s1 = km1 ? sc.y * scale : -1e9f;
            float m = fmaxf(s0, s1);
            #pragma unroll
            for (int o = 16; o; o >>= 1) m = fmaxf(m, __shfl_xor_sync(0xffffffffu, m, o));
            float e0 = __expf(s0 - m), e1 = __expf(s1 - m);
            float ss = e0 + e1;
            #pragma unroll
            for (int o = 16; o; o >>= 1) ss += __shfl_xor_sync(0xffffffffu, ss, o);
            float inv = 1.0f / ss;
            sm[P_OFF + t * 256 + ah * 64 + lane]      = e0 * inv;
            sm[P_OFF + t * 256 + ah * 64 + lane + 32] = e1 * inv;
        }
    }
    __syncthreads();

    // ================= O = P @ V -> Od =================
    {
        const int gb = ah * 32;
        float oacc[8] = {0,0,0,0,0,0,0,0};
        #pragma unroll 2
        for (int l = 0; l < LL; l += 4) {
            float v0 = sm[V_OFF + (l + 0) * FF + gb + lane];
            float v1 = sm[V_OFF + (l + 1) * FF + gb + lane];
            float v2 = sm[V_OFF + (l + 2) * FF + gb + lane];
            float v3 = sm[V_OFF + (l + 3) * FF + gb + lane];
            #pragma unroll
            for (int it = 0; it < 8; it++) {
                int tr = atw * 8 + it; tr = tr < TT ? tr : (TT - 1);
                float4 p = *(const float4*)&sm[P_OFF + tr * 256 + ah * 64 + l];
                oacc[it] = fmaf(p.x, v0, fmaf(p.y, v1, fmaf(p.z, v2, fmaf(p.w, v3, oacc[it]))));
            }
        }
        #pragma unroll
        for (int it = 0; it < 8; it++) {
            int t = atw * 8 + it;
            if (t < TT)
                sm[OD_OFF + t * 132 + gb + lane] = oacc[it];
        }
    }
    __syncthreads();

    // ================= Y = O @ Wc^T + residual =================
    {
        load_wpair2(sm, WC2_OFF, Wc, 0, tid);
        __syncthreads();

        u64 acc[8] = {0,0,0,0,0,0,0,0};
        const int wbase = WC2_OFF + fh * 4160;
        #pragma unroll
        for (int stage = 0; stage < 2; stage++) {
            const int fbase = fh * 64 + stage * 32;
            #pragma unroll 2
            for (int f4 = 0; f4 < 32; f4 += 4) {
                u64 w0 = *(const u64*)&sm[wbase + (f4 + 0) * 130 + gp];
                u64 w1 = *(const u64*)&sm[wbase + (f4 + 1) * 130 + gp];
                u64 w2 = *(const u64*)&sm[wbase + (f4 + 2) * 130 + gp];
                u64 w3 = *(const u64*)&sm[wbase + (f4 + 3) * 130 + gp];
                #pragma unroll
                for (int it = 0; it < 8; it++) {
                    int tr = tw * 8 + it; tr = tr < TT ? tr : (TT - 1);
                    float4 a = *(const float4*)&sm[OD_OFF + tr * 132 + fbase + f4];
                    acc[it] = ffma2(dup2(a.x), w0, acc[it]);
                    acc[it] = ffma2(dup2(a.y), w1, acc[it]);
                    acc[it] = ffma2(dup2(a.z), w2, acc[it]);
                    acc[it] = ffma2(dup2(a.w), w3, acc[it]);
                }
            }
            if (stage == 0) {
                __syncthreads();
                load_wpair2(sm, WC2_OFF, Wc, 1, tid);
                __syncthreads();
            }
        }
        if (fh == 1) {
            #pragma unroll
            for (int it = 0; it < 8; it++) {
                int t = tw * 8 + it;
                if (t < TT)
                    *(u64*)&sm[PB_OFF + (t * 64 + lane + 32 * gsub) * 2] = acc[it];
            }
        }
        __syncthreads();
        if (fh == 0) {
            #pragma unroll
            for (int it = 0; it < 8; it++) {
                int t = tw * 8 + it;
                if (t < TT) {
                    u64 part = *(const u64*)&sm[PB_OFF + (t * 64 + lane + 32 * gsub) * 2];
                    float2 v = unpack2(addf2(acc[it], part));
                    size_t o = (size_t)(t * NBLK + bid) * FF + gp;
                    float2 xv = *(const float2*)&veh[o];
                    v.x += xv.x; v.y += xv.y;
                    *(float2*)&out[o] = v;
                }
            }
        }
    }
}

extern "C" void kernel_launch(void* const* d_in, const int* in_sizes, int n_in,
                              void* d_out, int out_size)
{
    const float* veh   = (const float*)d_in[0];
    const float* lanes = (const float*)d_in[1];
    const int*   maskl = (const int*)d_in[2];
    const float* Wk    = (const float*)d_in[3];
    const float* Wv    = (const float*)d_in[4];
    const float* Wq    = (const float*)d_in[5];
    const float* Wc    = (const float*)d_in[6];

    const size_t smem = SMEM_FLOATS * sizeof(float); // 115712 B
    cudaFuncSetAttribute(lane_attn_kernel,
                         cudaFuncAttributeMaxDynamicSharedMemorySize, (int)smem);
    lane_attn_kernel<<<NBLK, NTHR, smem>>>(veh, lanes, maskl, Wk, Wv, Wq, Wc,
                                           (float*)d_out);
}